// round 2
// baseline (speedup 1.0000x reference)
#include <cuda_runtime.h>

// DisplacementVectorsASU:
//   in_frac  = frac_coords[edge_indices[0]]            (M,3)
//   out_frac = frac_coords[edge_indices[1]]            (M,3)
//   out_h    = [out_frac, 1]                           (M,4)
//   out_t[k] = dot(out_h, symmops[e,k,:])  k=0..2
//   out_t    = out_t - floor(out_t) + cell_translations
//   result   = in_frac - out_t
//
// Inputs (metadata order):
//   d_in[0] frac_coords       float32  (100000, 3)
//   d_in[1] edge_indices      int32    (2, 4000000)
//   d_in[2] symmops           float32  (4000000, 4, 4)
//   d_in[3] cell_translations float32  (4000000, 3)
// Output: float32 (4000000, 3)

__global__ __launch_bounds__(256)
void displacement_kernel(const float*  __restrict__ frac,
                         const int*    __restrict__ ei,
                         const float4* __restrict__ sym,   // 4 float4 per edge
                         const float*  __restrict__ ct,
                         float*        __restrict__ out,
                         int M)
{
    int e = blockIdx.x * blockDim.x + threadIdx.x;
    if (e >= M) return;

    // Gather indices (coalesced: two contiguous index streams)
    const int i0 = __ldg(ei + e);        // edge_indices[0][e]
    const int i1 = __ldg(ei + M + e);    // edge_indices[1][e]

    // Node coordinate gathers — table is 1.2MB, L2-resident
    const float ix = __ldg(frac + 3 * i0 + 0);
    const float iy = __ldg(frac + 3 * i0 + 1);
    const float iz = __ldg(frac + 3 * i0 + 2);

    const float ox = __ldg(frac + 3 * i1 + 0);
    const float oy = __ldg(frac + 3 * i1 + 1);
    const float oz = __ldg(frac + 3 * i1 + 2);

    // Symmop rows 0..2 (row 3 unused). 64B/edge contiguous -> float4 loads.
    const long sb = 4L * e;
    const float4 r0 = __ldg(sym + sb + 0);
    const float4 r1 = __ldg(sym + sb + 1);
    const float4 r2 = __ldg(sym + sb + 2);

    // Affine transform of homogeneous out coordinate
    float t0 = fmaf(r0.x, ox, fmaf(r0.y, oy, fmaf(r0.z, oz, r0.w)));
    float t1 = fmaf(r1.x, ox, fmaf(r1.y, oy, fmaf(r1.z, oz, r1.w)));
    float t2 = fmaf(r2.x, ox, fmaf(r2.y, oy, fmaf(r2.z, oz, r2.w)));

    // Periodic wrap + translation, then displacement
    const long cb = 3L * e;
    const float c0 = __ldg(ct + cb + 0);
    const float c1 = __ldg(ct + cb + 1);
    const float c2 = __ldg(ct + cb + 2);

    out[cb + 0] = ix - (t0 - floorf(t0) + c0);
    out[cb + 1] = iy - (t1 - floorf(t1) + c1);
    out[cb + 2] = iz - (t2 - floorf(t2) + c2);
}

extern "C" void kernel_launch(void* const* d_in, const int* in_sizes, int n_in,
                              void* d_out, int out_size)
{
    const float*  frac = (const float*) d_in[0];
    const int*    ei   = (const int*)   d_in[1];
    const float4* sym  = (const float4*)d_in[2];
    const float*  ct   = (const float*) d_in[3];
    float*        out  = (float*)       d_out;

    const int M = in_sizes[1] / 2;   // edge_indices has 2*M elements

    const int threads = 256;
    const int blocks  = (M + threads - 1) / threads;
    displacement_kernel<<<blocks, threads>>>(frac, ei, sym, ct, out, M);
}

// round 3
// speedup vs baseline: 1.0674x; 1.0674x over previous
#include <cuda_runtime.h>

// DisplacementVectorsASU — HBM-bound gather + per-edge affine transform.
//
// Inputs (metadata order):
//   d_in[0] frac_coords       float32  (100000, 3)
//   d_in[1] edge_indices      int32    (2, 4000000)
//   d_in[2] symmops           float32  (4000000, 4, 4)
//   d_in[3] cell_translations float32  (4000000, 3)
// Output: float32 (4000000, 3)
//
// Strategy:
//  - Pre-pass packs frac_coords (stride 12B) into a float4 table (16B) in a
//    __device__ scratch array, so each per-edge node gather is a single
//    LDG.128 hitting one 32B sector per lane (vs 3 divergent LDG.32).
//  - cell_translations and the output are staged through shared memory with
//    cooperative float4 loads/stores; per-thread smem access at stride 3 is
//    bank-conflict-free (gcd(3,32)=1).

#define NODE_CAP 131072
__device__ float4 g_frac4[NODE_CAP];

__global__ __launch_bounds__(256)
void pack_frac_kernel(const float* __restrict__ frac, int n)
{
    int i = blockIdx.x * blockDim.x + threadIdx.x;
    if (i < n) {
        float4 v;
        v.x = frac[3 * i + 0];
        v.y = frac[3 * i + 1];
        v.z = frac[3 * i + 2];
        v.w = 0.0f;
        g_frac4[i] = v;
    }
}

__global__ __launch_bounds__(256)
void displacement_kernel(const int*    __restrict__ ei,
                         const float4* __restrict__ sym,   // 4 float4 per edge
                         const float4* __restrict__ ct4,   // ct viewed as float4
                         float4*       __restrict__ out4,  // out viewed as float4
                         int M)
{
    __shared__ float s_ct[768];    // 256 edges * 3 floats
    __shared__ float s_out[768];

    const int tid       = threadIdx.x;
    const int blockBase = blockIdx.x * 256;
    const int e         = blockBase + tid;

    // ---- cooperative, fully-coalesced float4 load of cell_translations ----
    // Block covers floats [3*blockBase, 3*blockBase + 768) = 192 float4.
    {
        const long f4base = (long)blockBase * 3 / 4;     // blockBase % 4 == 0
        if (tid < 192) {
            long idx = f4base + tid;
            if (idx * 4 < (long)M * 3) {                 // tail guard
                ((float4*)s_ct)[tid] = __ldg(ct4 + idx);
            }
        }
    }
    __syncthreads();

    if (e < M) {
        // Edge endpoint indices (two coalesced streams)
        const int i0 = __ldg(ei + e);
        const int i1 = __ldg(ei + M + e);

        // Node coordinate gathers — single LDG.128 each, L2-resident table
        const float4 fin = __ldg(g_frac4 + i0);
        const float4 fo  = __ldg(g_frac4 + i1);

        // Symmop rows 0..2 (row 3 unused)
        const long sb = 4L * e;
        const float4 r0 = __ldg(sym + sb + 0);
        const float4 r1 = __ldg(sym + sb + 1);
        const float4 r2 = __ldg(sym + sb + 2);

        float t0 = fmaf(r0.x, fo.x, fmaf(r0.y, fo.y, fmaf(r0.z, fo.z, r0.w)));
        float t1 = fmaf(r1.x, fo.x, fmaf(r1.y, fo.y, fmaf(r1.z, fo.z, r1.w)));
        float t2 = fmaf(r2.x, fo.x, fmaf(r2.y, fo.y, fmaf(r2.z, fo.z, r2.w)));

        const float c0 = s_ct[3 * tid + 0];
        const float c1 = s_ct[3 * tid + 1];
        const float c2 = s_ct[3 * tid + 2];

        s_out[3 * tid + 0] = fin.x - (t0 - floorf(t0) + c0);
        s_out[3 * tid + 1] = fin.y - (t1 - floorf(t1) + c1);
        s_out[3 * tid + 2] = fin.z - (t2 - floorf(t2) + c2);
    }
    __syncthreads();

    // ---- cooperative, fully-coalesced float4 store of the output ----
    {
        const long f4base = (long)blockBase * 3 / 4;
        if (tid < 192) {
            long idx = f4base + tid;
            if (idx * 4 < (long)M * 3) {
                out4[idx] = ((const float4*)s_out)[tid];
            }
        }
    }
}

extern "C" void kernel_launch(void* const* d_in, const int* in_sizes, int n_in,
                              void* d_out, int out_size)
{
    const float*  frac = (const float*) d_in[0];
    const int*    ei   = (const int*)   d_in[1];
    const float4* sym  = (const float4*)d_in[2];
    const float4* ct4  = (const float4*)d_in[3];
    float4*       out4 = (float4*)      d_out;

    const int n = in_sizes[0] / 3;      // node count
    const int M = in_sizes[1] / 2;      // edge count

    pack_frac_kernel<<<(n + 255) / 256, 256>>>(frac, n);

    const int threads = 256;
    const int blocks  = (M + threads - 1) / threads;
    displacement_kernel<<<blocks, threads>>>(ei, sym, ct4, out4, M);
}